// round 2
// baseline (speedup 1.0000x reference)
#include <cuda_runtime.h>
#include <cuda_bf16.h>
#include <math.h>

// Problem constants
#define BB 8
#define NN 384
#define DIN 512
#define DM 512

// Device scratch (allocation-free requirement -> __device__ globals)
__device__ float g_G[DIN * DM];            // Wq^T Wk  (1 MB)
__device__ float g_P[BB * NN * DM];        // h @ G    (6 MB)
__device__ float g_w2[DIN];                // Wk^T bq
__device__ float g_left[BB * NN];
__device__ float g_right[BB * NN];
__device__ float g_bias[BB * NN];          // h_j . w2
__device__ float g_logp[BB * NN * NN];     // 4.7 MB
__device__ float g_log1mp[BB * NN * NN];   // 4.7 MB

// ---------------------------------------------------------------------------
// w2[v] = sum_m bq[m] * Wk[m, v]
// ---------------------------------------------------------------------------
__global__ void __launch_bounds__(128) w2_kernel(
    const float* __restrict__ Wk, const float* __restrict__ bq)
{
    const int v = blockIdx.x * 128 + threadIdx.x;
    float s = 0.f;
    for (int m = 0; m < DM; m++)
        s = fmaf(bq[m], Wk[(size_t)m * DIN + v], s);
    g_w2[v] = s;
}

// ---------------------------------------------------------------------------
// G[u,v] = sum_m Wq[m,u] * Wk[m,v]   (K dim = m, row dim of W -> direct loads)
// 64x64 tiles, K-chunk 16, 256 threads, 4x4 per thread.
// ---------------------------------------------------------------------------
__global__ void __launch_bounds__(256) gram_kernel(
    const float* __restrict__ Wq, const float* __restrict__ Wk)
{
    __shared__ float As[16][68];
    __shared__ float Bs[16][68];

    const int u0 = blockIdx.y * 64;
    const int v0 = blockIdx.x * 64;
    const int tid = threadIdx.x;
    const int r  = tid >> 4;        // 0..15 k-row
    const int c4 = (tid & 15) * 4;  // 0..60 col
    const int tx = tid & 15;
    const int ty = tid >> 4;

    float acc[4][4];
#pragma unroll
    for (int a = 0; a < 4; a++)
#pragma unroll
        for (int b = 0; b < 4; b++) acc[a][b] = 0.f;

    for (int k0 = 0; k0 < DM; k0 += 16) {
        float4 av = *(const float4*)&Wq[(size_t)(k0 + r) * DIN + u0 + c4];
        float4 bv = *(const float4*)&Wk[(size_t)(k0 + r) * DIN + v0 + c4];
        As[r][c4 + 0] = av.x; As[r][c4 + 1] = av.y;
        As[r][c4 + 2] = av.z; As[r][c4 + 3] = av.w;
        Bs[r][c4 + 0] = bv.x; Bs[r][c4 + 1] = bv.y;
        Bs[r][c4 + 2] = bv.z; Bs[r][c4 + 3] = bv.w;
        __syncthreads();
#pragma unroll
        for (int kk = 0; kk < 16; kk++) {
            float ar[4], br[4];
#pragma unroll
            for (int ii = 0; ii < 4; ii++) ar[ii] = As[kk][ty * 4 + ii];
#pragma unroll
            for (int jj = 0; jj < 4; jj++) br[jj] = Bs[kk][tx * 4 + jj];
#pragma unroll
            for (int ii = 0; ii < 4; ii++)
#pragma unroll
                for (int jj = 0; jj < 4; jj++)
                    acc[ii][jj] = fmaf(ar[ii], br[jj], acc[ii][jj]);
        }
        __syncthreads();
    }

#pragma unroll
    for (int ii = 0; ii < 4; ii++)
#pragma unroll
        for (int jj = 0; jj < 4; jj++)
            g_G[(size_t)(u0 + ty * 4 + ii) * DM + v0 + tx * 4 + jj] = acc[ii][jj];
}

// ---------------------------------------------------------------------------
// P[i,v] = sum_u h[i,u] * G[u,v]. A = h (K-contiguous -> transposed smem
// store), B = G (K = row dim -> direct smem store).
// ---------------------------------------------------------------------------
__global__ void __launch_bounds__(256) p_gemm(const float* __restrict__ h)
{
    __shared__ float As[16][68];
    __shared__ float Bs[16][68];

    const int m0 = blockIdx.y * 64;
    const int v0 = blockIdx.x * 64;
    const int tid = threadIdx.x;
    const int lr = tid >> 2;        // A: 0..63 row
    const int lc = tid & 3;         // A: 0..3 k-float4
    const int r  = tid >> 4;        // B: 0..15 k-row
    const int c4 = (tid & 15) * 4;  // B: col
    const int tx = tid & 15;
    const int ty = tid >> 4;

    float acc[4][4];
#pragma unroll
    for (int a = 0; a < 4; a++)
#pragma unroll
        for (int b = 0; b < 4; b++) acc[a][b] = 0.f;

    for (int k0 = 0; k0 < DIN; k0 += 16) {
        float4 av = *(const float4*)&h[(size_t)(m0 + lr) * DIN + k0 + lc * 4];
        float4 bv = *(const float4*)&g_G[(size_t)(k0 + r) * DM + v0 + c4];
        As[lc * 4 + 0][lr] = av.x; As[lc * 4 + 1][lr] = av.y;
        As[lc * 4 + 2][lr] = av.z; As[lc * 4 + 3][lr] = av.w;
        Bs[r][c4 + 0] = bv.x; Bs[r][c4 + 1] = bv.y;
        Bs[r][c4 + 2] = bv.z; Bs[r][c4 + 3] = bv.w;
        __syncthreads();
#pragma unroll
        for (int kk = 0; kk < 16; kk++) {
            float ar[4], br[4];
#pragma unroll
            for (int ii = 0; ii < 4; ii++) ar[ii] = As[kk][ty * 4 + ii];
#pragma unroll
            for (int jj = 0; jj < 4; jj++) br[jj] = Bs[kk][tx * 4 + jj];
#pragma unroll
            for (int ii = 0; ii < 4; ii++)
#pragma unroll
                for (int jj = 0; jj < 4; jj++)
                    acc[ii][jj] = fmaf(ar[ii], br[jj], acc[ii][jj]);
        }
        __syncthreads();
    }

#pragma unroll
    for (int ii = 0; ii < 4; ii++)
#pragma unroll
        for (int jj = 0; jj < 4; jj++)
            g_P[(size_t)(m0 + ty * 4 + ii) * DM + v0 + tx * 4 + jj] = acc[ii][jj];
}

// ---------------------------------------------------------------------------
// left/right/bias projections, one warp per row (3 dots fused).
// ---------------------------------------------------------------------------
__global__ void __launch_bounds__(256) lr_kernel(
    const float* __restrict__ h,
    const float* __restrict__ wlr, const float* __restrict__ blr,
    const float* __restrict__ wrl, const float* __restrict__ brl)
{
    const int row = blockIdx.x * 8 + (threadIdx.x >> 5);
    const int lane = threadIdx.x & 31;
    const float* hr = h + (size_t)row * DIN;
    float sl = 0.f, sr = 0.f, sb = 0.f;
    for (int d = lane; d < DIN; d += 32) {
        float hv = hr[d];
        sl = fmaf(hv, wlr[d], sl);
        sr = fmaf(hv, wrl[d], sr);
        sb = fmaf(hv, g_w2[d], sb);
    }
#pragma unroll
    for (int o = 16; o; o >>= 1) {
        sl += __shfl_down_sync(0xFFFFFFFFu, sl, o);
        sr += __shfl_down_sync(0xFFFFFFFFu, sr, o);
        sb += __shfl_down_sync(0xFFFFFFFFu, sb, o);
    }
    if (lane == 0) {
        g_left[row]  = sl + blr[0];
        g_right[row] = sr + brl[0];
        g_bias[row]  = sb;
    }
}

// ---------------------------------------------------------------------------
// S[b,i,j] = sum_v P[b,i,v] h[b,j,v] + bias[b,j], fused logsigmoid epilogue.
// ---------------------------------------------------------------------------
__global__ void __launch_bounds__(256) scores_kernel(
    const float* __restrict__ h,
    const float* __restrict__ alpha_p,
    const float* __restrict__ beta_p,
    const float* __restrict__ gamma_p)
{
    const int b = blockIdx.z;
    const float* __restrict__ Pb = g_P + (size_t)b * NN * DM;
    const float* __restrict__ Hb = h   + (size_t)b * NN * DIN;

    __shared__ float As[16][68];
    __shared__ float Bs[16][68];

    const int m0 = blockIdx.y * 64;   // i tile
    const int o0 = blockIdx.x * 64;   // j tile
    const int tid = threadIdx.x;
    const int lr = tid >> 2;
    const int lc = tid & 3;
    const int tx = tid & 15;
    const int ty = tid >> 4;

    float acc[4][4];
#pragma unroll
    for (int a = 0; a < 4; a++)
#pragma unroll
        for (int c = 0; c < 4; c++) acc[a][c] = 0.f;

    for (int k0 = 0; k0 < DM; k0 += 16) {
        float4 av = *(const float4*)&Pb[(size_t)(m0 + lr) * DM + k0 + lc * 4];
        float4 bv = *(const float4*)&Hb[(size_t)(o0 + lr) * DIN + k0 + lc * 4];
        As[lc * 4 + 0][lr] = av.x; As[lc * 4 + 1][lr] = av.y;
        As[lc * 4 + 2][lr] = av.z; As[lc * 4 + 3][lr] = av.w;
        Bs[lc * 4 + 0][lr] = bv.x; Bs[lc * 4 + 1][lr] = bv.y;
        Bs[lc * 4 + 2][lr] = bv.z; Bs[lc * 4 + 3][lr] = bv.w;
        __syncthreads();
#pragma unroll
        for (int kk = 0; kk < 16; kk++) {
            float ar[4], br[4];
#pragma unroll
            for (int ii = 0; ii < 4; ii++) ar[ii] = As[kk][ty * 4 + ii];
#pragma unroll
            for (int jj = 0; jj < 4; jj++) br[jj] = Bs[kk][tx * 4 + jj];
#pragma unroll
            for (int ii = 0; ii < 4; ii++)
#pragma unroll
                for (int jj = 0; jj < 4; jj++)
                    acc[ii][jj] = fmaf(ar[ii], br[jj], acc[ii][jj]);
        }
        __syncthreads();
    }

    const float alpha = alpha_p[0];
    const float beta  = beta_p[0];
    const float gamma = gamma_p[0];

    float* lp_base = g_logp   + (size_t)b * NN * NN;
    float* l1_base = g_log1mp + (size_t)b * NN * NN;

#pragma unroll
    for (int ii = 0; ii < 4; ii++) {
        const int i = m0 + ty * 4 + ii;
        const float lft = g_left[b * NN + i];
        const float rgt = g_right[b * NN + i];
#pragma unroll
        for (int jj = 0; jj < 4; jj++) {
            const int j = o0 + tx * 4 + jj;
            const float sc = acc[ii][jj] + g_bias[b * NN + j];
            const float dv = (j >= i) ? lft : rgt;
            float raw = alpha * sc + beta * dv + gamma;
            raw = fminf(fmaxf(raw, -16.f), 14.f);
            const float lp = -log1pf(expf(-raw));   // log sigmoid(raw)
            const float l1 = lp - raw;              // log sigmoid(-raw)
            lp_base[(size_t)i * NN + j] = lp;
            l1_base[(size_t)i * NN + j] = l1;
        }
    }
}

// ---------------------------------------------------------------------------
// finalize: per-(b,i) row: prefix sum of log_1mp -> interval sums -> r.
//   i<j: k in (i, j) and [max(2i-j+1,0), i)
//   i>j: k in (j, i) and (i, min(2i-j, N-1)]
// ---------------------------------------------------------------------------
__global__ void __launch_bounds__(NN) finalize_kernel(
    const float* __restrict__ mask,
    float* __restrict__ r_out,
    float* __restrict__ am_out)
{
    const int bi = blockIdx.x;           // b * N + i
    const int b = bi / NN;
    const int i = bi - b * NN;
    const int j = threadIdx.x;           // 0..383

    __shared__ float S[NN + 1];
    __shared__ float warpsum[12];

    const float v = g_log1mp[(size_t)bi * NN + j];

    float x = v;
#pragma unroll
    for (int o = 1; o < 32; o <<= 1) {
        float y = __shfl_up_sync(0xFFFFFFFFu, x, o);
        if ((j & 31) >= o) x += y;
    }
    if ((j & 31) == 31) warpsum[j >> 5] = x;
    __syncthreads();
    if (j < 12) {
        float w = warpsum[j];
#pragma unroll
        for (int o = 1; o < 12; o <<= 1) {
            float y = __shfl_up_sync(0x00000FFFu, w, o);
            if (j >= o) w += y;
        }
        warpsum[j] = w;
    }
    __syncthreads();
    float incl = x + ((j >= 32) ? warpsum[(j >> 5) - 1] : 0.f);
    S[j + 1] = incl;
    if (j == 0) S[0] = 0.f;
    __syncthreads();

    const float lp = g_logp[(size_t)bi * NN + j];
    float a;
    if (i == j) {
        a = lp - 10000.f;
    } else if (i < j) {
        const int lo = max(2 * i - j + 1, 0);
        a = lp + (S[j] - S[i + 1]) + (S[i] - S[lo]);
    } else {
        const int hi = min(2 * i - j, NN - 1);
        a = lp + (S[i] - S[j + 1]) + (S[hi + 1] - S[i + 1]);
    }

    r_out[(size_t)bi * NN + j] = a;
    if (am_out) {
        am_out[(size_t)bi * NN + j] = mask[b * NN + i] * mask[b * NN + j];
    }
}

// ---------------------------------------------------------------------------
// Launch. Inputs: h, mask, Wq, bq, Wk, wlr, blr, wrl, brl, alpha, beta,
// gamma, masking_matrix (unused — closed-form intervals).
// ---------------------------------------------------------------------------
extern "C" void kernel_launch(void* const* d_in, const int* in_sizes, int n_in,
                              void* d_out, int out_size)
{
    const float* h     = (const float*)d_in[0];
    const float* mask  = (const float*)d_in[1];
    const float* Wq    = (const float*)d_in[2];
    const float* bq    = (const float*)d_in[3];
    const float* Wk    = (const float*)d_in[4];
    const float* wlr   = (const float*)d_in[5];
    const float* blr   = (const float*)d_in[6];
    const float* wrl   = (const float*)d_in[7];
    const float* brl   = (const float*)d_in[8];
    const float* alpha = (const float*)d_in[9];
    const float* beta  = (const float*)d_in[10];
    const float* gamma = (const float*)d_in[11];

    float* r_out = (float*)d_out;
    const long long BNN = (long long)BB * NN * NN;
    float* am_out = (out_size >= 2 * BNN) ? (r_out + BNN) : nullptr;

    // w2 = Wk^T bq
    w2_kernel<<<DIN / 128, 128>>>(Wk, bq);
    // G = Wq^T Wk
    {
        dim3 grid(DM / 64, DIN / 64);
        gram_kernel<<<grid, 256>>>(Wq, Wk);
    }
    // left/right/bias (depends on w2)
    lr_kernel<<<(BB * NN) / 8, 256>>>(h, wlr, blr, wrl, brl);
    // P = h @ G
    {
        dim3 grid(DM / 64, (BB * NN) / 64);
        p_gemm<<<grid, 256>>>(h);
    }
    // S = P @ h^T + bias, fused logsigmoid
    {
        dim3 grid(NN / 64, NN / 64, BB);
        scores_kernel<<<grid, 256>>>(h, alpha, beta, gamma);
    }
    // scan + assembly
    finalize_kernel<<<BB * NN, NN>>>(mask, r_out, am_out);
}

// round 4
// speedup vs baseline: 2.1216x; 2.1216x over previous
#include <cuda_runtime.h>
#include <cuda_bf16.h>
#include <math.h>
#include <stdint.h>

#define BB 8
#define NN 384
#define DD 512
#define BN (BB * NN)   // 3072
#define SMROW 80       // smem bytes per 32-bf16 row (64B data + 16B pad)

// ---------------- device scratch ----------------
__device__ __nv_bfloat16 g_hh[BN * DD], g_hl[BN * DD];
__device__ __nv_bfloat16 g_wqh[DD * DD], g_wql[DD * DD];
__device__ __nv_bfloat16 g_wkh[DD * DD], g_wkl[DD * DD];
__device__ __nv_bfloat16 g_qh[BN * DD], g_ql[BN * DD];
__device__ __nv_bfloat16 g_kh[BN * DD], g_kl[BN * DD];
__device__ float g_left[BN], g_right[BN];
__device__ float g_raw[(size_t)BB * NN * NN];

// ---------------- helpers ----------------
__device__ __forceinline__ uint32_t smem_u32(const void* p) {
    uint32_t a;
    asm("{ .reg .u64 t; cvta.to.shared.u64 t, %1; cvt.u32.u64 %0, t; }"
        : "=r"(a) : "l"(p));
    return a;
}

__device__ __forceinline__ void ldsm4(uint32_t* r, uint32_t addr) {
    asm volatile("ldmatrix.sync.aligned.m8n8.x4.shared.b16 {%0,%1,%2,%3}, [%4];"
                 : "=r"(r[0]), "=r"(r[1]), "=r"(r[2]), "=r"(r[3]) : "r"(addr));
}

__device__ __forceinline__ void mma16816(float* c, const uint32_t* a, const uint32_t* b) {
    asm volatile(
        "mma.sync.aligned.m16n8k16.row.col.f32.bf16.bf16.f32 "
        "{%0,%1,%2,%3}, {%4,%5,%6,%7}, {%8,%9}, {%0,%1,%2,%3};"
        : "+f"(c[0]), "+f"(c[1]), "+f"(c[2]), "+f"(c[3])
        : "r"(a[0]), "r"(a[1]), "r"(a[2]), "r"(a[3]), "r"(b[0]), "r"(b[1]));
}

__device__ __forceinline__ void split_store2(
    __nv_bfloat16* oh, __nv_bfloat16* ol, size_t idx, float v0, float v1)
{
    __nv_bfloat16 h0 = __float2bfloat16(v0);
    __nv_bfloat16 h1 = __float2bfloat16(v1);
    __nv_bfloat162 hp; hp.x = h0; hp.y = h1;
    *(__nv_bfloat162*)(oh + idx) = hp;
    __nv_bfloat162 lp;
    lp.x = __float2bfloat16(v0 - __bfloat162float(h0));
    lp.y = __float2bfloat16(v1 - __bfloat162float(h1));
    *(__nv_bfloat162*)(ol + idx) = lp;
}

// ---------------------------------------------------------------------------
// prep: split h, Wq, Wk into bf16 hi/lo. 1024 blocks x 256 thr x 8 elems.
// ---------------------------------------------------------------------------
__global__ void __launch_bounds__(256) prep_kernel(
    const float* __restrict__ h,
    const float* __restrict__ Wq,
    const float* __restrict__ Wk)
{
    const int blk = blockIdx.x;
    const float* src;
    __nv_bfloat16 *dh, *dl;
    long base;
    if (blk < 768)      { src = h;  dh = g_hh;  dl = g_hl;  base = (long)blk * 2048; }
    else if (blk < 896) { src = Wq; dh = g_wqh; dl = g_wql; base = (long)(blk - 768) * 2048; }
    else                { src = Wk; dh = g_wkh; dl = g_wkl; base = (long)(blk - 896) * 2048; }

    const long o = base + (long)threadIdx.x * 8;
    float4 x0 = *(const float4*)(src + o);
    float4 x1 = *(const float4*)(src + o + 4);
    float v[8] = {x0.x, x0.y, x0.z, x0.w, x1.x, x1.y, x1.z, x1.w};
#pragma unroll
    for (int e = 0; e < 8; e++) {
        __nv_bfloat16 hi = __float2bfloat16(v[e]);
        dh[o + e] = hi;
        dl[o + e] = __float2bfloat16(v[e] - __bfloat162float(hi));
    }
}

// ---------------------------------------------------------------------------
// left/right projections, one warp per row.
// ---------------------------------------------------------------------------
__global__ void __launch_bounds__(256) lr_kernel(
    const float* __restrict__ h,
    const float* __restrict__ wlr, const float* __restrict__ blr,
    const float* __restrict__ wrl, const float* __restrict__ brl)
{
    const int row = blockIdx.x * 8 + (threadIdx.x >> 5);
    const int lane = threadIdx.x & 31;
    const float* hr = h + (size_t)row * DD;
    float sl = 0.f, sr = 0.f;
    for (int d = lane; d < DD; d += 32) {
        float hv = hr[d];
        sl = fmaf(hv, wlr[d], sl);
        sr = fmaf(hv, wrl[d], sr);
    }
#pragma unroll
    for (int o = 16; o; o >>= 1) {
        sl += __shfl_down_sync(0xFFFFFFFFu, sl, o);
        sr += __shfl_down_sync(0xFFFFFFFFu, sr, o);
    }
    if (lane == 0) {
        g_left[row]  = sl + blr[0];
        g_right[row] = sr + brl[0];
    }
}

// ---------------------------------------------------------------------------
// GEMM core: C[128 x NTILE] += A[128 x 512] * B[NTILE x 512]^T with
// split-bf16 3-term MMA. 256 threads = 8 warps (4 M x 2 N).
// Both operands K-contiguous; ldmatrix non-trans.
// ---------------------------------------------------------------------------
template<int NTILE>
__device__ __forceinline__ void gemm_core(
    const __nv_bfloat16* __restrict__ Ah, const __nv_bfloat16* __restrict__ Al,
    const __nv_bfloat16* __restrict__ Bh, const __nv_bfloat16* __restrict__ Bl,
    char* smem, float acc[2][NTILE / 16][4])
{
    const int tid = threadIdx.x;
    const int wid = tid >> 5, lane = tid & 31;
    const int wm = wid & 3, wn = wid >> 2;
    constexpr int NP = NTILE / 32;     // n8-pairs per warp

    char* sAh = smem;
    char* sAl = sAh + 128 * SMROW;
    char* sBh = sAl + 128 * SMROW;
    char* sBl = sBh + NTILE * SMROW;
    const uint32_t aAh = smem_u32(sAh), aAl = smem_u32(sAl);
    const uint32_t aBh = smem_u32(sBh), aBl = smem_u32(sBl);

    // ldmatrix per-lane address offsets
    const uint32_t a_off = (uint32_t)(lane & 15) * SMROW + (uint32_t)(lane >> 4) * 16;
    const uint32_t b_off = (uint32_t)((lane & 7) + ((lane >> 4) << 3)) * SMROW
                         + (uint32_t)((lane >> 3) & 1) * 16;

    for (int k0 = 0; k0 < DD; k0 += 32) {
        for (int idx = tid; idx < 128 * 4; idx += 256) {
            const int r = idx >> 2, g = idx & 3;
            const uint32_t so = r * SMROW + g * 16;
            const size_t go = (size_t)r * DD + k0 + g * 8;
            *(uint4*)(sAh + so) = *(const uint4*)(Ah + go);
            *(uint4*)(sAl + so) = *(const uint4*)(Al + go);
        }
        for (int idx = tid; idx < NTILE * 4; idx += 256) {
            const int r = idx >> 2, g = idx & 3;
            const uint32_t so = r * SMROW + g * 16;
            const size_t go = (size_t)r * DD + k0 + g * 8;
            *(uint4*)(sBh + so) = *(const uint4*)(Bh + go);
            *(uint4*)(sBl + so) = *(const uint4*)(Bl + go);
        }
        __syncthreads();

#pragma unroll
        for (int ks = 0; ks < 2; ks++) {
            const uint32_t kb = ks * 32;
            uint32_t ah[2][4], al[2][4];
#pragma unroll
            for (int mf = 0; mf < 2; mf++) {
                const uint32_t rb = (uint32_t)(wm * 32 + mf * 16) * SMROW + kb + a_off;
                ldsm4(ah[mf], aAh + rb);
                ldsm4(al[mf], aAl + rb);
            }
#pragma unroll
            for (int np = 0; np < NP; np++) {
                const uint32_t nb = (uint32_t)(wn * (NTILE / 2) + np * 16) * SMROW + kb + b_off;
                uint32_t bh[4], bl[4];
                ldsm4(bh, aBh + nb);
                ldsm4(bl, aBl + nb);
#pragma unroll
                for (int mf = 0; mf < 2; mf++) {
                    mma16816(acc[mf][np * 2],     ah[mf], bh);
                    mma16816(acc[mf][np * 2 + 1], ah[mf], bh + 2);
                    mma16816(acc[mf][np * 2],     ah[mf], bl);
                    mma16816(acc[mf][np * 2 + 1], ah[mf], bl + 2);
                    mma16816(acc[mf][np * 2],     al[mf], bh);
                    mma16816(acc[mf][np * 2 + 1], al[mf], bh + 2);
                }
            }
        }
        __syncthreads();
    }
}

// ---------------------------------------------------------------------------
// proj: q = h Wq^T + bq (z=0), k = h Wk^T (z=1). Split-store to q/k pairs.
// ---------------------------------------------------------------------------
__global__ void __launch_bounds__(256) proj_kernel(const float* __restrict__ bq)
{
    __shared__ char smem[(128 + 128) * SMROW * 2];   // 40960 B
    const int n0 = blockIdx.x * 128;
    const int m0 = blockIdx.y * 128;
    const int z  = blockIdx.z;

    const __nv_bfloat16* Bh = (z ? g_wkh : g_wqh) + (size_t)n0 * DD;
    const __nv_bfloat16* Bl = (z ? g_wkl : g_wql) + (size_t)n0 * DD;

    float acc[2][8][4];
#pragma unroll
    for (int a = 0; a < 2; a++)
#pragma unroll
        for (int f = 0; f < 8; f++)
#pragma unroll
            for (int e = 0; e < 4; e++) acc[a][f][e] = 0.f;

    gemm_core<128>(g_hh + (size_t)m0 * DD, g_hl + (size_t)m0 * DD, Bh, Bl, smem, acc);

    const int wid = threadIdx.x >> 5, lane = threadIdx.x & 31;
    const int wm = wid & 3, wn = wid >> 2;
    __nv_bfloat16* oh = z ? g_kh : g_qh;
    __nv_bfloat16* ol = z ? g_kl : g_ql;

#pragma unroll
    for (int mf = 0; mf < 2; mf++) {
        const int r0 = m0 + wm * 32 + mf * 16 + (lane >> 2);
#pragma unroll
        for (int f = 0; f < 8; f++) {
            const int c = n0 + wn * 64 + f * 8 + (lane & 3) * 2;
            const float b0 = z ? 0.f : __ldg(&bq[c]);
            const float b1 = z ? 0.f : __ldg(&bq[c + 1]);
            split_store2(oh, ol, (size_t)r0 * DD + c,
                         acc[mf][f][0] + b0, acc[mf][f][1] + b1);
            split_store2(oh, ol, (size_t)(r0 + 8) * DD + c,
                         acc[mf][f][2] + b0, acc[mf][f][3] + b1);
        }
    }
}

// ---------------------------------------------------------------------------
// scores: per-batch S = q k^T, 128x64 tiles, fused raw-score epilogue.
// ---------------------------------------------------------------------------
__global__ void __launch_bounds__(256) scores_kernel(
    const float* __restrict__ alpha_p,
    const float* __restrict__ beta_p,
    const float* __restrict__ gamma_p)
{
    __shared__ char smem[(128 + 64) * SMROW * 2];    // 30720 B
    const int b  = blockIdx.z;
    const int m0 = blockIdx.y * 128;
    const int n0 = blockIdx.x * 64;
    const size_t abase = ((size_t)b * NN + m0) * DD;
    const size_t bbase = ((size_t)b * NN + n0) * DD;

    float acc[2][4][4];
#pragma unroll
    for (int a = 0; a < 2; a++)
#pragma unroll
        for (int f = 0; f < 4; f++)
#pragma unroll
            for (int e = 0; e < 4; e++) acc[a][f][e] = 0.f;

    gemm_core<64>(g_qh + abase, g_ql + abase, g_kh + bbase, g_kl + bbase, smem, acc);

    const float alpha = alpha_p[0], beta = beta_p[0], gamma = gamma_p[0];
    const int wid = threadIdx.x >> 5, lane = threadIdx.x & 31;
    const int wm = wid & 3, wn = wid >> 2;

#pragma unroll
    for (int mf = 0; mf < 2; mf++) {
        const int rl = m0 + wm * 32 + mf * 16 + (lane >> 2);
#pragma unroll
        for (int rr = 0; rr < 2; rr++) {
            const int i = rl + rr * 8;                     // row within batch
            const float lft = g_left[b * NN + i];
            const float rgt = g_right[b * NN + i];
            float* rb = g_raw + ((size_t)b * NN + i) * NN;
#pragma unroll
            for (int f = 0; f < 4; f++) {
                const int j = n0 + wn * 32 + f * 8 + (lane & 3) * 2;
                float2 o;
                {
                    const float dv = (j >= i) ? lft : rgt;
                    float raw = fmaf(alpha, acc[mf][f][rr * 2],
                                     fmaf(beta, dv, gamma));
                    o.x = fminf(fmaxf(raw, -16.f), 14.f);
                }
                {
                    const float dv = (j + 1 >= i) ? lft : rgt;
                    float raw = fmaf(alpha, acc[mf][f][rr * 2 + 1],
                                     fmaf(beta, dv, gamma));
                    o.y = fminf(fmaxf(raw, -16.f), 14.f);
                }
                *(float2*)(rb + j) = o;
            }
        }
    }
}

// ---------------------------------------------------------------------------
// finalize: per-(b,i) row: logsigmoid + prefix sum + interval sums -> r, am.
//   i<j: k in (i, j) and [max(2i-j+1,0), i)
//   i>j: k in (j, i) and (i, min(2i-j, N-1)]
// ---------------------------------------------------------------------------
__global__ void __launch_bounds__(NN) finalize_kernel(
    const float* __restrict__ mask,
    float* __restrict__ r_out,
    float* __restrict__ am_out)
{
    const int bi = blockIdx.x;
    const int b = bi / NN;
    const int i = bi - b * NN;
    const int j = threadIdx.x;

    __shared__ float S[NN + 1];
    __shared__ float warpsum[12];

    const float raw = g_raw[(size_t)bi * NN + j];
    const float l1 = -log1pf(expf(raw));    // log sigmoid(-raw)
    const float lp = raw + l1;              // log sigmoid(raw)

    float x = l1;
#pragma unroll
    for (int o = 1; o < 32; o <<= 1) {
        float y = __shfl_up_sync(0xFFFFFFFFu, x, o);
        if ((j & 31) >= o) x += y;
    }
    if ((j & 31) == 31) warpsum[j >> 5] = x;
    __syncthreads();
    if (j < 12) {
        float w = warpsum[j];
#pragma unroll
        for (int o = 1; o < 12; o <<= 1) {
            float y = __shfl_up_sync(0x00000FFFu, w, o);
            if (j >= o) w += y;
        }
        warpsum[j] = w;
    }
    __syncthreads();
    float incl = x + ((j >= 32) ? warpsum[(j >> 5) - 1] : 0.f);
    S[j + 1] = incl;
    if (j == 0) S[0] = 0.f;
    __syncthreads();

    float a;
    if (i == j) {
        a = lp - 10000.f;
    } else if (i < j) {
        const int lo = max(2 * i - j + 1, 0);
        a = lp + (S[j] - S[i + 1]) + (S[i] - S[lo]);
    } else {
        const int hi = min(2 * i - j, NN - 1);
        a = lp + (S[i] - S[j + 1]) + (S[hi + 1] - S[i + 1]);
    }

    r_out[(size_t)bi * NN + j] = a;
    if (am_out)
        am_out[(size_t)bi * NN + j] = mask[b * NN + i] * mask[b * NN + j];
}

// ---------------------------------------------------------------------------
// Launch. Inputs: h, mask, Wq, bq, Wk, wlr, blr, wrl, brl, alpha, beta,
// gamma, masking_matrix (unused — closed-form intervals).
// ---------------------------------------------------------------------------
extern "C" void kernel_launch(void* const* d_in, const int* in_sizes, int n_in,
                              void* d_out, int out_size)
{
    const float* h     = (const float*)d_in[0];
    const float* mask  = (const float*)d_in[1];
    const float* Wq    = (const float*)d_in[2];
    const float* bq    = (const float*)d_in[3];
    const float* Wk    = (const float*)d_in[4];
    const float* wlr   = (const float*)d_in[5];
    const float* blr   = (const float*)d_in[6];
    const float* wrl   = (const float*)d_in[7];
    const float* brl   = (const float*)d_in[8];
    const float* alpha = (const float*)d_in[9];
    const float* beta  = (const float*)d_in[10];
    const float* gamma = (const float*)d_in[11];

    float* r_out = (float*)d_out;
    const long long BNN = (long long)BB * NN * NN;
    float* am_out = (out_size >= 2 * BNN) ? (r_out + BNN) : nullptr;

    prep_kernel<<<1024, 256>>>(h, Wq, Wk);
    lr_kernel<<<BN / 8, 256>>>(h, wlr, blr, wrl, brl);
    proj_kernel<<<dim3(4, 24, 2), 256>>>(bq);
    scores_kernel<<<dim3(6, 3, 8), 256>>>(alpha, beta, gamma);
    finalize_kernel<<<BB * NN, NN>>>(mask, r_out, am_out);
}

// round 5
// speedup vs baseline: 2.9124x; 1.3728x over previous
#include <cuda_runtime.h>
#include <cuda_bf16.h>
#include <math.h>
#include <stdint.h>

#define BB 8
#define NN 384
#define DD 512
#define BN (BB * NN)   // 3072
#define SMROW 80       // smem bytes per 32-bf16 row (64B data + 16B pad)

// ---------------- device scratch ----------------
__device__ __nv_bfloat16 g_hh[BN * DD], g_hl[BN * DD];
__device__ __nv_bfloat16 g_wqh[DD * DD], g_wql[DD * DD];
__device__ __nv_bfloat16 g_wkh[DD * DD], g_wkl[DD * DD];
__device__ __nv_bfloat16 g_qh[BN * DD], g_ql[BN * DD];
__device__ __nv_bfloat16 g_kh[BN * DD], g_kl[BN * DD];
__device__ float g_left[BN], g_right[BN];
__device__ float g_raw[(size_t)BB * NN * NN];

// ---------------- helpers ----------------
__device__ __forceinline__ uint32_t smem_u32(const void* p) {
    uint32_t a;
    asm("{ .reg .u64 t; cvta.to.shared.u64 t, %1; cvt.u32.u64 %0, t; }"
        : "=r"(a) : "l"(p));
    return a;
}

__device__ __forceinline__ void cp16(uint32_t dst, const void* src) {
    asm volatile("cp.async.cg.shared.global [%0], [%1], 16;"
                 :: "r"(dst), "l"(src) : "memory");
}
#define CP_COMMIT() asm volatile("cp.async.commit_group;" ::: "memory")

__device__ __forceinline__ void ldsm4(uint32_t* r, uint32_t addr) {
    asm volatile("ldmatrix.sync.aligned.m8n8.x4.shared.b16 {%0,%1,%2,%3}, [%4];"
                 : "=r"(r[0]), "=r"(r[1]), "=r"(r[2]), "=r"(r[3]) : "r"(addr));
}

__device__ __forceinline__ void mma16816(float* c, const uint32_t* a, const uint32_t* b) {
    asm volatile(
        "mma.sync.aligned.m16n8k16.row.col.f32.bf16.bf16.f32 "
        "{%0,%1,%2,%3}, {%4,%5,%6,%7}, {%8,%9}, {%0,%1,%2,%3};"
        : "+f"(c[0]), "+f"(c[1]), "+f"(c[2]), "+f"(c[3])
        : "r"(a[0]), "r"(a[1]), "r"(a[2]), "r"(a[3]), "r"(b[0]), "r"(b[1]));
}

__device__ __forceinline__ void split_store2(
    __nv_bfloat16* oh, __nv_bfloat16* ol, size_t idx, float v0, float v1)
{
    __nv_bfloat16 h0 = __float2bfloat16(v0);
    __nv_bfloat16 h1 = __float2bfloat16(v1);
    __nv_bfloat162 hp; hp.x = h0; hp.y = h1;
    *(__nv_bfloat162*)(oh + idx) = hp;
    __nv_bfloat162 lp;
    lp.x = __float2bfloat16(v0 - __bfloat162float(h0));
    lp.y = __float2bfloat16(v1 - __bfloat162float(h1));
    *(__nv_bfloat162*)(ol + idx) = lp;
}

// ---------------------------------------------------------------------------
// prep + lr fused. Blocks 0..1023: bf16 hi/lo splits. Blocks 1024..1407: lr.
// ---------------------------------------------------------------------------
__global__ void __launch_bounds__(256) prep_kernel(
    const float* __restrict__ h,
    const float* __restrict__ Wq,
    const float* __restrict__ Wk,
    const float* __restrict__ wlr, const float* __restrict__ blr,
    const float* __restrict__ wrl, const float* __restrict__ brl)
{
    const int blk = blockIdx.x;
    if (blk < 1024) {
        const float* src;
        __nv_bfloat16 *dh, *dl;
        long base;
        if (blk < 768)      { src = h;  dh = g_hh;  dl = g_hl;  base = (long)blk * 2048; }
        else if (blk < 896) { src = Wq; dh = g_wqh; dl = g_wql; base = (long)(blk - 768) * 2048; }
        else                { src = Wk; dh = g_wkh; dl = g_wkl; base = (long)(blk - 896) * 2048; }

        const long o = base + (long)threadIdx.x * 8;
        float4 x0 = *(const float4*)(src + o);
        float4 x1 = *(const float4*)(src + o + 4);
        float v[8] = {x0.x, x0.y, x0.z, x0.w, x1.x, x1.y, x1.z, x1.w};
#pragma unroll
        for (int e = 0; e < 8; e++) {
            __nv_bfloat16 hi = __float2bfloat16(v[e]);
            dh[o + e] = hi;
            dl[o + e] = __float2bfloat16(v[e] - __bfloat162float(hi));
        }
    } else {
        const int row = (blk - 1024) * 8 + (threadIdx.x >> 5);
        const int lane = threadIdx.x & 31;
        const float* hr = h + (size_t)row * DD;
        float sl = 0.f, sr = 0.f;
        for (int d = lane; d < DD; d += 32) {
            float hv = hr[d];
            sl = fmaf(hv, wlr[d], sl);
            sr = fmaf(hv, wrl[d], sr);
        }
#pragma unroll
        for (int o = 16; o; o >>= 1) {
            sl += __shfl_down_sync(0xFFFFFFFFu, sl, o);
            sr += __shfl_down_sync(0xFFFFFFFFu, sr, o);
        }
        if (lane == 0) {
            g_left[row]  = sl + blr[0];
            g_right[row] = sr + brl[0];
        }
    }
}

// ---------------------------------------------------------------------------
// Double-buffered split-bf16 GEMM core.
// Tile M = MW*MF*16, N = NW*NF*8, K = 512 in 16 chunks of 32.
// Stage layout: Ah | Al | Bh | Bl, rows of SMROW bytes.
// ---------------------------------------------------------------------------
template<int MW, int NW, int MF, int NF>
__device__ __forceinline__ void gemm_db(
    const __nv_bfloat16* __restrict__ Ah, const __nv_bfloat16* __restrict__ Al,
    const __nv_bfloat16* __restrict__ Bh, const __nv_bfloat16* __restrict__ Bl,
    char* smem, float acc[MF][NF][4])
{
    constexpr int MT = MW * MF * 16;
    constexpr int NT = NW * NF * 8;
    constexpr int A_BYTES = MT * SMROW;
    constexpr int B_BYTES = NT * SMROW;
    constexpr int STAGE = 2 * A_BYTES + 2 * B_BYTES;
    constexpr int NTHR = MW * NW * 32;

    const int tid = threadIdx.x;
    const int wid = tid >> 5, lane = tid & 31;
    const int wm = wid % MW, wn = wid / MW;
    const uint32_t s0 = smem_u32(smem);

    const uint32_t a_off = (uint32_t)(lane & 15) * SMROW + (uint32_t)(lane >> 4) * 16;
    const uint32_t b_off = (uint32_t)((lane & 7) + ((lane >> 4) << 3)) * SMROW
                         + (uint32_t)((lane >> 3) & 1) * 16;

#pragma unroll 1
    for (int c = -1; c < 16; c++) {
        // issue loads for chunk c+1
        if (c < 15) {
            const int cc = c + 1;
            const int k0 = cc * 32;
            const uint32_t sb = s0 + (cc & 1) * STAGE;
#pragma unroll
            for (int idx = tid; idx < MT * 4; idx += NTHR) {
                const int r = idx >> 2, g = idx & 3;
                const uint32_t so = (uint32_t)r * SMROW + g * 16;
                const size_t go = (size_t)r * DD + k0 + g * 8;
                cp16(sb + so, Ah + go);
                cp16(sb + A_BYTES + so, Al + go);
            }
#pragma unroll
            for (int idx = tid; idx < NT * 4; idx += NTHR) {
                const int r = idx >> 2, g = idx & 3;
                const uint32_t so = (uint32_t)r * SMROW + g * 16;
                const size_t go = (size_t)r * DD + k0 + g * 8;
                cp16(sb + 2 * A_BYTES + so, Bh + go);
                cp16(sb + 2 * A_BYTES + B_BYTES + so, Bl + go);
            }
            CP_COMMIT();
        }
        if (c < 0) continue;   // prologue: only issued chunk 0

        if (c < 15) asm volatile("cp.async.wait_group 1;" ::: "memory");
        else        asm volatile("cp.async.wait_group 0;" ::: "memory");
        __syncthreads();

        const uint32_t sb = s0 + (c & 1) * STAGE;
#pragma unroll
        for (int ks = 0; ks < 2; ks++) {
            const uint32_t kb = ks * 32;
            uint32_t ahf[MF][4], alf[MF][4];
#pragma unroll
            for (int mf = 0; mf < MF; mf++) {
                const uint32_t rb = (uint32_t)(wm * MF * 16 + mf * 16) * SMROW + kb + a_off;
                ldsm4(ahf[mf], sb + rb);
                ldsm4(alf[mf], sb + A_BYTES + rb);
            }
#pragma unroll
            for (int np = 0; np < NF / 2; np++) {
                const uint32_t nb = (uint32_t)(wn * NF * 8 + np * 16) * SMROW + kb + b_off;
                uint32_t bh[4], bl[4];
                ldsm4(bh, sb + 2 * A_BYTES + nb);
                ldsm4(bl, sb + 2 * A_BYTES + B_BYTES + nb);
#pragma unroll
                for (int mf = 0; mf < MF; mf++) {
                    mma16816(acc[mf][np * 2],     ahf[mf], bh);
                    mma16816(acc[mf][np * 2 + 1], ahf[mf], bh + 2);
                    mma16816(acc[mf][np * 2],     ahf[mf], bl);
                    mma16816(acc[mf][np * 2 + 1], ahf[mf], bl + 2);
                    mma16816(acc[mf][np * 2],     alf[mf], bh);
                    mma16816(acc[mf][np * 2 + 1], alf[mf], bh + 2);
                }
            }
        }
        __syncthreads();
    }
}

// ---------------------------------------------------------------------------
// proj: q = h Wq^T + bq (z=0), k = h Wk^T (z=1). Tile 128x64. Grid (8,24,2).
// ---------------------------------------------------------------------------
__global__ void __launch_bounds__(256) proj_kernel(const float* __restrict__ bq)
{
    extern __shared__ char smem[];
    const int n0 = blockIdx.x * 64;
    const int m0 = blockIdx.y * 128;
    const int z  = blockIdx.z;

    const __nv_bfloat16* Bh = (z ? g_wkh : g_wqh) + (size_t)n0 * DD;
    const __nv_bfloat16* Bl = (z ? g_wkl : g_wql) + (size_t)n0 * DD;

    float acc[2][4][4];
#pragma unroll
    for (int a = 0; a < 2; a++)
#pragma unroll
        for (int f = 0; f < 4; f++)
#pragma unroll
            for (int e = 0; e < 4; e++) acc[a][f][e] = 0.f;

    gemm_db<4, 2, 2, 4>(g_hh + (size_t)m0 * DD, g_hl + (size_t)m0 * DD,
                        Bh, Bl, smem, acc);

    const int wid = threadIdx.x >> 5, lane = threadIdx.x & 31;
    const int wm = wid & 3, wn = wid >> 2;
    __nv_bfloat16* oh = z ? g_kh : g_qh;
    __nv_bfloat16* ol = z ? g_kl : g_ql;

#pragma unroll
    for (int mf = 0; mf < 2; mf++) {
        const int r0 = m0 + wm * 32 + mf * 16 + (lane >> 2);
#pragma unroll
        for (int f = 0; f < 4; f++) {
            const int c = n0 + wn * 32 + f * 8 + (lane & 3) * 2;
            const float b0 = z ? 0.f : __ldg(&bq[c]);
            const float b1 = z ? 0.f : __ldg(&bq[c + 1]);
            split_store2(oh, ol, (size_t)r0 * DD + c,
                         acc[mf][f][0] + b0, acc[mf][f][1] + b1);
            split_store2(oh, ol, (size_t)(r0 + 8) * DD + c,
                         acc[mf][f][2] + b0, acc[mf][f][3] + b1);
        }
    }
}

// ---------------------------------------------------------------------------
// scores: per-batch S = q k^T, tile 64x64. Grid (6,6,8) = 288 CTAs.
// Epilogue: raw = clip(alpha*S + beta*d + gamma) -> g_raw.
// ---------------------------------------------------------------------------
__global__ void __launch_bounds__(256) scores_kernel(
    const float* __restrict__ alpha_p,
    const float* __restrict__ beta_p,
    const float* __restrict__ gamma_p)
{
    extern __shared__ char smem[];
    const int b  = blockIdx.z;
    const int m0 = blockIdx.y * 64;
    const int n0 = blockIdx.x * 64;
    const size_t abase = ((size_t)b * NN + m0) * DD;
    const size_t bbase = ((size_t)b * NN + n0) * DD;

    float acc[2][2][4];
#pragma unroll
    for (int a = 0; a < 2; a++)
#pragma unroll
        for (int f = 0; f < 2; f++)
#pragma unroll
            for (int e = 0; e < 4; e++) acc[a][f][e] = 0.f;

    gemm_db<2, 4, 2, 2>(g_qh + abase, g_ql + abase,
                        g_kh + bbase, g_kl + bbase, smem, acc);

    const float alpha = alpha_p[0], beta = beta_p[0], gamma = gamma_p[0];
    const int wid = threadIdx.x >> 5, lane = threadIdx.x & 31;
    const int wm = wid & 1, wn = wid >> 1;

#pragma unroll
    for (int mf = 0; mf < 2; mf++) {
        const int rl = m0 + wm * 32 + mf * 16 + (lane >> 2);
#pragma unroll
        for (int rr = 0; rr < 2; rr++) {
            const int i = rl + rr * 8;
            const float lft = g_left[b * NN + i];
            const float rgt = g_right[b * NN + i];
            float* rb = g_raw + ((size_t)b * NN + i) * NN;
#pragma unroll
            for (int f = 0; f < 2; f++) {
                const int j = n0 + wn * 16 + f * 8 + (lane & 3) * 2;
                float2 o;
                {
                    const float dv = (j >= i) ? lft : rgt;
                    float raw = fmaf(alpha, acc[mf][f][rr * 2],
                                     fmaf(beta, dv, gamma));
                    o.x = fminf(fmaxf(raw, -16.f), 14.f);
                }
                {
                    const float dv = (j + 1 >= i) ? lft : rgt;
                    float raw = fmaf(alpha, acc[mf][f][rr * 2 + 1],
                                     fmaf(beta, dv, gamma));
                    o.y = fminf(fmaxf(raw, -16.f), 14.f);
                }
                *(float2*)(rb + j) = o;
            }
        }
    }
}

// ---------------------------------------------------------------------------
// finalize: per-(b,i) row: logsigmoid + prefix sum + interval sums -> r, am.
// ---------------------------------------------------------------------------
__global__ void __launch_bounds__(NN) finalize_kernel(
    const float* __restrict__ mask,
    float* __restrict__ r_out,
    float* __restrict__ am_out)
{
    const int bi = blockIdx.x;
    const int b = bi / NN;
    const int i = bi - b * NN;
    const int j = threadIdx.x;

    __shared__ float S[NN + 1];
    __shared__ float warpsum[12];

    const float raw = g_raw[(size_t)bi * NN + j];
    const float l1 = -log1pf(expf(raw));    // log sigmoid(-raw)
    const float lp = raw + l1;              // log sigmoid(raw)

    float x = l1;
#pragma unroll
    for (int o = 1; o < 32; o <<= 1) {
        float y = __shfl_up_sync(0xFFFFFFFFu, x, o);
        if ((j & 31) >= o) x += y;
    }
    if ((j & 31) == 31) warpsum[j >> 5] = x;
    __syncthreads();
    if (j < 12) {
        float w = warpsum[j];
#pragma unroll
        for (int o = 1; o < 12; o <<= 1) {
            float y = __shfl_up_sync(0x00000FFFu, w, o);
            if (j >= o) w += y;
        }
        warpsum[j] = w;
    }
    __syncthreads();
    float incl = x + ((j >= 32) ? warpsum[(j >> 5) - 1] : 0.f);
    S[j + 1] = incl;
    if (j == 0) S[0] = 0.f;
    __syncthreads();

    float a;
    if (i == j) {
        a = lp - 10000.f;
    } else if (i < j) {
        const int lo = max(2 * i - j + 1, 0);
        a = lp + (S[j] - S[i + 1]) + (S[i] - S[lo]);
    } else {
        const int hi = min(2 * i - j, NN - 1);
        a = lp + (S[i] - S[j + 1]) + (S[hi + 1] - S[i + 1]);
    }

    r_out[(size_t)bi * NN + j] = a;
    if (am_out)
        am_out[(size_t)bi * NN + j] = mask[b * NN + i] * mask[b * NN + j];
}

// ---------------------------------------------------------------------------
// Launch
// ---------------------------------------------------------------------------
extern "C" void kernel_launch(void* const* d_in, const int* in_sizes, int n_in,
                              void* d_out, int out_size)
{
    const float* h     = (const float*)d_in[0];
    const float* mask  = (const float*)d_in[1];
    const float* Wq    = (const float*)d_in[2];
    const float* bq    = (const float*)d_in[3];
    const float* Wk    = (const float*)d_in[4];
    const float* wlr   = (const float*)d_in[5];
    const float* blr   = (const float*)d_in[6];
    const float* wrl   = (const float*)d_in[7];
    const float* brl   = (const float*)d_in[8];
    const float* alpha = (const float*)d_in[9];
    const float* beta  = (const float*)d_in[10];
    const float* gamma = (const float*)d_in[11];

    float* r_out = (float*)d_out;
    const long long BNN = (long long)BB * NN * NN;
    float* am_out = (out_size >= 2 * BNN) ? (r_out + BNN) : nullptr;

    // proj stage: (2*128 + 2*64)*80 = 30720 B, 2 stages = 61440 B
    // scores stage: (2*64 + 2*64)*80 = 20480 B, 2 stages = 40960 B
    static bool attr_set = false;
    const int proj_smem = 61440, scores_smem = 40960;
    if (!attr_set) {
        cudaFuncSetAttribute(proj_kernel,
                             cudaFuncAttributeMaxDynamicSharedMemorySize, proj_smem);
        cudaFuncSetAttribute(scores_kernel,
                             cudaFuncAttributeMaxDynamicSharedMemorySize, scores_smem);
        attr_set = true;
    }

    prep_kernel<<<1408, 256>>>(h, Wq, Wk, wlr, blr, wrl, brl);
    proj_kernel<<<dim3(8, 24, 2), 256, proj_smem>>>(bq);
    scores_kernel<<<dim3(6, 6, 8), 256, scores_smem>>>(alpha, beta, gamma);
    finalize_kernel<<<BB * NN, NN>>>(mask, r_out, am_out);
}

// round 6
// speedup vs baseline: 2.9837x; 1.0245x over previous
#include <cuda_runtime.h>
#include <cuda_bf16.h>
#include <math.h>
#include <stdint.h>

#define BB 8
#define NN 384
#define DD 512
#define BN (BB * NN)   // 3072
#define SMROW 80       // smem bytes per 32-bf16 row (64B data + 16B pad)

// ---------------- device scratch ----------------
__device__ __nv_bfloat16 g_hh[BN * DD], g_hl[BN * DD];
__device__ __nv_bfloat16 g_wqh[DD * DD], g_wql[DD * DD];
__device__ __nv_bfloat16 g_wkh[DD * DD], g_wkl[DD * DD];
__device__ __nv_bfloat16 g_qh[BN * DD], g_ql[BN * DD];
__device__ __nv_bfloat16 g_kh[BN * DD], g_kl[BN * DD];
__device__ float g_left[BN], g_right[BN];
__device__ float g_raw[(size_t)BB * NN * NN];

// ---------------- helpers ----------------
__device__ __forceinline__ uint32_t smem_u32(const void* p) {
    uint32_t a;
    asm("{ .reg .u64 t; cvta.to.shared.u64 t, %1; cvt.u32.u64 %0, t; }"
        : "=r"(a) : "l"(p));
    return a;
}

__device__ __forceinline__ void cp16(uint32_t dst, const void* src) {
    asm volatile("cp.async.cg.shared.global [%0], [%1], 16;"
                 :: "r"(dst), "l"(src) : "memory");
}
#define CP_COMMIT() asm volatile("cp.async.commit_group;" ::: "memory")

__device__ __forceinline__ void ldsm4(uint32_t* r, uint32_t addr) {
    asm volatile("ldmatrix.sync.aligned.m8n8.x4.shared.b16 {%0,%1,%2,%3}, [%4];"
                 : "=r"(r[0]), "=r"(r[1]), "=r"(r[2]), "=r"(r[3]) : "r"(addr));
}

__device__ __forceinline__ void mma16816(float* c, const uint32_t* a, const uint32_t* b) {
    asm volatile(
        "mma.sync.aligned.m16n8k16.row.col.f32.bf16.bf16.f32 "
        "{%0,%1,%2,%3}, {%4,%5,%6,%7}, {%8,%9}, {%0,%1,%2,%3};"
        : "+f"(c[0]), "+f"(c[1]), "+f"(c[2]), "+f"(c[3])
        : "r"(a[0]), "r"(a[1]), "r"(a[2]), "r"(a[3]), "r"(b[0]), "r"(b[1]));
}

__device__ __forceinline__ void split_store2(
    __nv_bfloat16* oh, __nv_bfloat16* ol, size_t idx, float v0, float v1)
{
    __nv_bfloat16 h0 = __float2bfloat16(v0);
    __nv_bfloat16 h1 = __float2bfloat16(v1);
    __nv_bfloat162 hp; hp.x = h0; hp.y = h1;
    *(__nv_bfloat162*)(oh + idx) = hp;
    __nv_bfloat162 lp;
    lp.x = __float2bfloat16(v0 - __bfloat162float(h0));
    lp.y = __float2bfloat16(v1 - __bfloat162float(h1));
    *(__nv_bfloat162*)(ol + idx) = lp;
}

// ---------------------------------------------------------------------------
// prep + lr fused. Blocks 0..1023: bf16 hi/lo splits. Blocks 1024..1407: lr.
// ---------------------------------------------------------------------------
__global__ void __launch_bounds__(256) prep_kernel(
    const float* __restrict__ h,
    const float* __restrict__ Wq,
    const float* __restrict__ Wk,
    const float* __restrict__ wlr, const float* __restrict__ blr,
    const float* __restrict__ wrl, const float* __restrict__ brl)
{
    const int blk = blockIdx.x;
    if (blk < 1024) {
        const float* src;
        __nv_bfloat16 *dh, *dl;
        long base;
        if (blk < 768)      { src = h;  dh = g_hh;  dl = g_hl;  base = (long)blk * 2048; }
        else if (blk < 896) { src = Wq; dh = g_wqh; dl = g_wql; base = (long)(blk - 768) * 2048; }
        else                { src = Wk; dh = g_wkh; dl = g_wkl; base = (long)(blk - 896) * 2048; }

        const long o = base + (long)threadIdx.x * 8;
        float4 x0 = *(const float4*)(src + o);
        float4 x1 = *(const float4*)(src + o + 4);
        float v[8] = {x0.x, x0.y, x0.z, x0.w, x1.x, x1.y, x1.z, x1.w};
#pragma unroll
        for (int e = 0; e < 8; e++) {
            __nv_bfloat16 hi = __float2bfloat16(v[e]);
            dh[o + e] = hi;
            dl[o + e] = __float2bfloat16(v[e] - __bfloat162float(hi));
        }
    } else {
        const int row = (blk - 1024) * 8 + (threadIdx.x >> 5);
        const int lane = threadIdx.x & 31;
        const float* hr = h + (size_t)row * DD;
        float sl = 0.f, sr = 0.f;
        for (int d = lane; d < DD; d += 32) {
            float hv = hr[d];
            sl = fmaf(hv, wlr[d], sl);
            sr = fmaf(hv, wrl[d], sr);
        }
#pragma unroll
        for (int o = 16; o; o >>= 1) {
            sl += __shfl_down_sync(0xFFFFFFFFu, sl, o);
            sr += __shfl_down_sync(0xFFFFFFFFu, sr, o);
        }
        if (lane == 0) {
            g_left[row]  = sl + blr[0];
            g_right[row] = sr + brl[0];
        }
    }
}

// ---------------------------------------------------------------------------
// Multi-stage split-bf16 GEMM core (STAGES = 2 or 3).
// Tile M = MW*MF*16, N = NW*NF*8, K = 512 in 16 chunks of 32.
// Stage layout: Ah | Al | Bh | Bl, rows of SMROW bytes.
// ---------------------------------------------------------------------------
template<int MW, int NW, int MF, int NF, int STAGES>
__device__ __forceinline__ void gemm_db(
    const __nv_bfloat16* __restrict__ Ah, const __nv_bfloat16* __restrict__ Al,
    const __nv_bfloat16* __restrict__ Bh, const __nv_bfloat16* __restrict__ Bl,
    char* smem, float acc[MF][NF][4])
{
    constexpr int MT = MW * MF * 16;
    constexpr int NT = NW * NF * 8;
    constexpr int A_BYTES = MT * SMROW;
    constexpr int B_BYTES = NT * SMROW;
    constexpr int STAGE = 2 * A_BYTES + 2 * B_BYTES;
    constexpr int NTHR = MW * NW * 32;

    const int tid = threadIdx.x;
    const int wid = tid >> 5, lane = tid & 31;
    const int wm = wid % MW, wn = wid / MW;
    const uint32_t s0 = smem_u32(smem);

    const uint32_t a_off = (uint32_t)(lane & 15) * SMROW + (uint32_t)(lane >> 4) * 16;
    const uint32_t b_off = (uint32_t)((lane & 7) + ((lane >> 4) << 3)) * SMROW
                         + (uint32_t)((lane >> 3) & 1) * 16;

    // issue loads for chunk cc into its stage
    auto issue = [&](int cc) {
        const int k0 = cc * 32;
        const uint32_t sb = s0 + (cc % STAGES) * STAGE;
#pragma unroll
        for (int idx = tid; idx < MT * 4; idx += NTHR) {
            const int r = idx >> 2, g = idx & 3;
            const uint32_t so = (uint32_t)r * SMROW + g * 16;
            const size_t go = (size_t)r * DD + k0 + g * 8;
            cp16(sb + so, Ah + go);
            cp16(sb + A_BYTES + so, Al + go);
        }
#pragma unroll
        for (int idx = tid; idx < NT * 4; idx += NTHR) {
            const int r = idx >> 2, g = idx & 3;
            const uint32_t so = (uint32_t)r * SMROW + g * 16;
            const size_t go = (size_t)r * DD + k0 + g * 8;
            cp16(sb + 2 * A_BYTES + so, Bh + go);
            cp16(sb + 2 * A_BYTES + B_BYTES + so, Bl + go);
        }
        CP_COMMIT();
    };

    // prologue: fill STAGES-1 stages
#pragma unroll
    for (int p = 0; p < STAGES - 1; p++) issue(p);

#pragma unroll 1
    for (int c = 0; c < 16; c++) {
        if (c + STAGES - 1 < 16) issue(c + STAGES - 1);

        const int rem = 15 - c;     // chunks beyond c still wanted in flight
        if (STAGES == 2) {
            if (rem >= 1) asm volatile("cp.async.wait_group 1;" ::: "memory");
            else          asm volatile("cp.async.wait_group 0;" ::: "memory");
        } else {
            if (rem >= 2)      asm volatile("cp.async.wait_group 2;" ::: "memory");
            else if (rem == 1) asm volatile("cp.async.wait_group 1;" ::: "memory");
            else               asm volatile("cp.async.wait_group 0;" ::: "memory");
        }
        __syncthreads();

        const uint32_t sb = s0 + (c % STAGES) * STAGE;
#pragma unroll
        for (int ks = 0; ks < 2; ks++) {
            const uint32_t kb = ks * 32;
            uint32_t ahf[MF][4], alf[MF][4];
#pragma unroll
            for (int mf = 0; mf < MF; mf++) {
                const uint32_t rb = (uint32_t)(wm * MF * 16 + mf * 16) * SMROW + kb + a_off;
                ldsm4(ahf[mf], sb + rb);
                ldsm4(alf[mf], sb + A_BYTES + rb);
            }
#pragma unroll
            for (int np = 0; np < NF / 2; np++) {
                const uint32_t nb = (uint32_t)(wn * NF * 8 + np * 16) * SMROW + kb + b_off;
                uint32_t bh[4], bl[4];
                ldsm4(bh, sb + 2 * A_BYTES + nb);
                ldsm4(bl, sb + 2 * A_BYTES + B_BYTES + nb);
#pragma unroll
                for (int mf = 0; mf < MF; mf++) {
                    mma16816(acc[mf][np * 2],     ahf[mf], bh);
                    mma16816(acc[mf][np * 2 + 1], ahf[mf], bh + 2);
                    mma16816(acc[mf][np * 2],     ahf[mf], bl);
                    mma16816(acc[mf][np * 2 + 1], ahf[mf], bl + 2);
                    mma16816(acc[mf][np * 2],     alf[mf], bh);
                    mma16816(acc[mf][np * 2 + 1], alf[mf], bh + 2);
                }
            }
        }
        __syncthreads();
    }
}

// ---------------------------------------------------------------------------
// proj: q = h Wq^T + bq (z=0), k = h Wk^T (z=1). Tile 128x64, 2-stage.
// ---------------------------------------------------------------------------
__global__ void __launch_bounds__(256) proj_kernel(const float* __restrict__ bq)
{
    extern __shared__ char smem[];
    const int n0 = blockIdx.x * 64;
    const int m0 = blockIdx.y * 128;
    const int z  = blockIdx.z;

    const __nv_bfloat16* Bh = (z ? g_wkh : g_wqh) + (size_t)n0 * DD;
    const __nv_bfloat16* Bl = (z ? g_wkl : g_wql) + (size_t)n0 * DD;

    float acc[2][4][4];
#pragma unroll
    for (int a = 0; a < 2; a++)
#pragma unroll
        for (int f = 0; f < 4; f++)
#pragma unroll
            for (int e = 0; e < 4; e++) acc[a][f][e] = 0.f;

    gemm_db<4, 2, 2, 4, 2>(g_hh + (size_t)m0 * DD, g_hl + (size_t)m0 * DD,
                           Bh, Bl, smem, acc);

    const int wid = threadIdx.x >> 5, lane = threadIdx.x & 31;
    const int wm = wid & 3, wn = wid >> 2;
    __nv_bfloat16* oh = z ? g_kh : g_qh;
    __nv_bfloat16* ol = z ? g_kl : g_ql;

#pragma unroll
    for (int mf = 0; mf < 2; mf++) {
        const int r0 = m0 + wm * 32 + mf * 16 + (lane >> 2);
#pragma unroll
        for (int f = 0; f < 4; f++) {
            const int c = n0 + wn * 32 + f * 8 + (lane & 3) * 2;
            const float b0 = z ? 0.f : __ldg(&bq[c]);
            const float b1 = z ? 0.f : __ldg(&bq[c + 1]);
            split_store2(oh, ol, (size_t)r0 * DD + c,
                         acc[mf][f][0] + b0, acc[mf][f][1] + b1);
            split_store2(oh, ol, (size_t)(r0 + 8) * DD + c,
                         acc[mf][f][2] + b0, acc[mf][f][3] + b1);
        }
    }
}

// ---------------------------------------------------------------------------
// scores: per-batch S = q k^T, tile 64x64, 3-stage. Grid (6,6,8) = 288 CTAs.
// Epilogue: raw = clip(alpha*S + beta*d + gamma) -> g_raw.
// ---------------------------------------------------------------------------
__global__ void __launch_bounds__(256) scores_kernel(
    const float* __restrict__ alpha_p,
    const float* __restrict__ beta_p,
    const float* __restrict__ gamma_p)
{
    extern __shared__ char smem[];
    const int b  = blockIdx.z;
    const int m0 = blockIdx.y * 64;
    const int n0 = blockIdx.x * 64;
    const size_t abase = ((size_t)b * NN + m0) * DD;
    const size_t bbase = ((size_t)b * NN + n0) * DD;

    float acc[2][2][4];
#pragma unroll
    for (int a = 0; a < 2; a++)
#pragma unroll
        for (int f = 0; f < 2; f++)
#pragma unroll
            for (int e = 0; e < 4; e++) acc[a][f][e] = 0.f;

    gemm_db<2, 4, 2, 2, 3>(g_qh + abase, g_ql + abase,
                           g_kh + bbase, g_kl + bbase, smem, acc);

    const float alpha = alpha_p[0], beta = beta_p[0], gamma = gamma_p[0];
    const int wid = threadIdx.x >> 5, lane = threadIdx.x & 31;
    const int wm = wid & 1, wn = wid >> 1;

#pragma unroll
    for (int mf = 0; mf < 2; mf++) {
        const int rl = m0 + wm * 32 + mf * 16 + (lane >> 2);
#pragma unroll
        for (int rr = 0; rr < 2; rr++) {
            const int i = rl + rr * 8;
            const float lft = g_left[b * NN + i];
            const float rgt = g_right[b * NN + i];
            float* rb = g_raw + ((size_t)b * NN + i) * NN;
#pragma unroll
            for (int f = 0; f < 2; f++) {
                const int j = n0 + wn * 16 + f * 8 + (lane & 3) * 2;
                float2 o;
                {
                    const float dv = (j >= i) ? lft : rgt;
                    float raw = fmaf(alpha, acc[mf][f][rr * 2],
                                     fmaf(beta, dv, gamma));
                    o.x = fminf(fmaxf(raw, -16.f), 14.f);
                }
                {
                    const float dv = (j + 1 >= i) ? lft : rgt;
                    float raw = fmaf(alpha, acc[mf][f][rr * 2 + 1],
                                     fmaf(beta, dv, gamma));
                    o.y = fminf(fmaxf(raw, -16.f), 14.f);
                }
                *(float2*)(rb + j) = o;
            }
        }
    }
}

// ---------------------------------------------------------------------------
// finalize: per-(b,i) row: logsigmoid + prefix sum + interval sums -> r, am.
// Fast-math transcendentals: raw is clipped to [-16,14] so __expf is safe;
// cancellation in __logf(1+e) only matters when l1 ~ e (|error| < 1e-7 abs).
// ---------------------------------------------------------------------------
__global__ void __launch_bounds__(NN) finalize_kernel(
    const float* __restrict__ mask,
    float* __restrict__ r_out,
    float* __restrict__ am_out)
{
    const int bi = blockIdx.x;
    const int b = bi / NN;
    const int i = bi - b * NN;
    const int j = threadIdx.x;

    __shared__ float S[NN + 1];
    __shared__ float warpsum[12];

    const float raw = g_raw[(size_t)bi * NN + j];
    const float l1 = -__logf(1.f + __expf(raw));   // log sigmoid(-raw)
    const float lp = raw + l1;                     // log sigmoid(raw)

    float x = l1;
#pragma unroll
    for (int o = 1; o < 32; o <<= 1) {
        float y = __shfl_up_sync(0xFFFFFFFFu, x, o);
        if ((j & 31) >= o) x += y;
    }
    if ((j & 31) == 31) warpsum[j >> 5] = x;
    __syncthreads();
    if (j < 12) {
        float w = warpsum[j];
#pragma unroll
        for (int o = 1; o < 12; o <<= 1) {
            float y = __shfl_up_sync(0x00000FFFu, w, o);
            if (j >= o) w += y;
        }
        warpsum[j] = w;
    }
    __syncthreads();
    float incl = x + ((j >= 32) ? warpsum[(j >> 5) - 1] : 0.f);
    S[j + 1] = incl;
    if (j == 0) S[0] = 0.f;
    __syncthreads();

    float a;
    if (i == j) {
        a = lp - 10000.f;
    } else if (i < j) {
        const int lo = max(2 * i - j + 1, 0);
        a = lp + (S[j] - S[i + 1]) + (S[i] - S[lo]);
    } else {
        const int hi = min(2 * i - j, NN - 1);
        a = lp + (S[i] - S[j + 1]) + (S[hi + 1] - S[i + 1]);
    }

    r_out[(size_t)bi * NN + j] = a;
    if (am_out)
        am_out[(size_t)bi * NN + j] = mask[b * NN + i] * mask[b * NN + j];
}

// ---------------------------------------------------------------------------
// Launch
// ---------------------------------------------------------------------------
extern "C" void kernel_launch(void* const* d_in, const int* in_sizes, int n_in,
                              void* d_out, int out_size)
{
    const float* h     = (const float*)d_in[0];
    const float* mask  = (const float*)d_in[1];
    const float* Wq    = (const float*)d_in[2];
    const float* bq    = (const float*)d_in[3];
    const float* Wk    = (const float*)d_in[4];
    const float* wlr   = (const float*)d_in[5];
    const float* blr   = (const float*)d_in[6];
    const float* wrl   = (const float*)d_in[7];
    const float* brl   = (const float*)d_in[8];
    const float* alpha = (const float*)d_in[9];
    const float* beta  = (const float*)d_in[10];
    const float* gamma = (const float*)d_in[11];

    float* r_out = (float*)d_out;
    const long long BNN = (long long)BB * NN * NN;
    float* am_out = (out_size >= 2 * BNN) ? (r_out + BNN) : nullptr;

    // proj stage: (2*128 + 2*64)*80 = 30720 B * 2 stages = 61440 B
    // scores stage: (2*64 + 2*64)*80 = 20480 B * 3 stages = 61440 B
    static bool attr_set = false;
    const int proj_smem = 61440, scores_smem = 61440;
    if (!attr_set) {
        cudaFuncSetAttribute(proj_kernel,
                             cudaFuncAttributeMaxDynamicSharedMemorySize, proj_smem);
        cudaFuncSetAttribute(scores_kernel,
                             cudaFuncAttributeMaxDynamicSharedMemorySize, scores_smem);
        attr_set = true;
    }

    prep_kernel<<<1408, 256>>>(h, Wq, Wk, wlr, blr, wrl, brl);
    proj_kernel<<<dim3(8, 24, 2), 256, proj_smem>>>(bq);
    scores_kernel<<<dim3(6, 6, 8), 256, scores_smem>>>(alpha, beta, gamma);
    finalize_kernel<<<BB * NN, NN>>>(mask, r_out, am_out);
}